// round 2
// baseline (speedup 1.0000x reference)
#include <cuda_runtime.h>

#define FIN 100
#define HD  64
#define NMAX 100000
#define EMAX 3200000

// ---------------- scratch (device globals: no allocation allowed) -----------
__device__ float g_hA[NMAX * HD];
__device__ float g_hB[NMAX * HD];
__device__ int   g_cnt[NMAX];          // per-dst degree (counts)
__device__ int   g_rowstart[NMAX + 1]; // CSR row offsets
__device__ int   g_cursor[NMAX];       // fill cursors
__device__ int   g_csrc[EMAX];         // CSR: src node per slot
__device__ float g_cw[EMAX];           // CSR: edge weight per slot

// ---------------- embedding: h = relu(x @ W + b) ----------------------------
__global__ void embed_kernel(const float* __restrict__ x,
                             const float* __restrict__ W,
                             const float* __restrict__ b,
                             float* __restrict__ h, int n) {
    int tid  = blockIdx.x * blockDim.x + threadIdx.x;
    int node = tid >> 6;
    int f    = tid & 63;
    if (node >= n) return;
    float acc = __ldg(&b[f]);
    const float* xr = x + (size_t)node * FIN;   // 400B-aligned rows
#pragma unroll
    for (int k = 0; k < FIN; k += 4) {
        float4 xv = *(const float4*)(xr + k);
        acc = fmaf(xv.x, __ldg(&W[(k + 0) * HD + f]), acc);
        acc = fmaf(xv.y, __ldg(&W[(k + 1) * HD + f]), acc);
        acc = fmaf(xv.z, __ldg(&W[(k + 2) * HD + f]), acc);
        acc = fmaf(xv.w, __ldg(&W[(k + 3) * HD + f]), acc);
    }
    h[tid] = fmaxf(acc, 0.0f);
}

// ---------------- CSR build (edge_index stored as int32, [2, E]) -------------
__global__ void hist_kernel(const int* __restrict__ ei, int e, int n) {
    int i = blockIdx.x * blockDim.x + threadIdx.x;
    if (i < e) {
        int dst = ei[e + i];
        dst = min(max(dst, 0), n - 1);   // safety clamp
        atomicAdd(&g_cnt[dst], 1);
    }
}

// single-block exclusive scan over g_cnt -> g_rowstart / g_cursor
__global__ void scan_kernel(int n) {
    __shared__ int swarp[32];
    __shared__ int scarry;
    int tid = threadIdx.x;
    if (tid == 0) scarry = 0;
    __syncthreads();
    for (int base = 0; base < n; base += 1024) {
        int i = base + tid;
        int v = (i < n) ? g_cnt[i] : 0;
        int xv = v;
#pragma unroll
        for (int o = 1; o < 32; o <<= 1) {
            int y = __shfl_up_sync(~0u, xv, o);
            if ((tid & 31) >= o) xv += y;
        }
        if ((tid & 31) == 31) swarp[tid >> 5] = xv;
        __syncthreads();
        if (tid < 32) {
            int y = swarp[tid];
#pragma unroll
            for (int o = 1; o < 32; o <<= 1) {
                int z = __shfl_up_sync(~0u, y, o);
                if (tid >= o) y += z;
            }
            swarp[tid] = y;
        }
        __syncthreads();
        int woff  = (tid >= 32) ? swarp[(tid >> 5) - 1] : 0;
        int excl  = xv - v + woff;
        int carry = scarry;
        if (i < n) {
            g_rowstart[i] = carry + excl;
            g_cursor[i]   = carry + excl;
        }
        int total = swarp[31];
        __syncthreads();
        if (tid == 0) scarry = carry + total;
        __syncthreads();
    }
    if (tid == 0) g_rowstart[n] = scarry;
}

__global__ void fill_kernel(const int* __restrict__ ei,
                            const float* __restrict__ w, int e, int n) {
    int i = blockIdx.x * blockDim.x + threadIdx.x;
    if (i < e) {
        int dst = ei[e + i];
        int src = ei[i];
        dst = min(max(dst, 0), n - 1);   // safety clamp
        src = min(max(src, 0), n - 1);
        int pos = atomicAdd(&g_cursor[dst], 1);
        pos = min(max(pos, 0), EMAX - 1);
        g_csrc[pos] = src;
        g_cw[pos]   = w[i];
    }
}

// ---------------- fused SAGE layer -------------------------------------------
// one warp per node: gather-mean over CSR neighbors, then
// out = mean @ Wl + bl + h @ Wr ; L2-normalize ; optional relu.
template <int COUT, bool USE_W, bool RELU>
__global__ void sage_kernel(const float* __restrict__ hin,
                            const float* __restrict__ Wl,
                            const float* __restrict__ bl,
                            const float* __restrict__ Wr,
                            float* __restrict__ hout, int n) {
    __shared__ float  sWl[HD * COUT];
    __shared__ float  sWr[HD * COUT];
    __shared__ float  sb[COUT];
    __shared__ float2 smv[8][HD];   // per-warp (mean[k], root[k])
    __shared__ int    sid[8][32];
    __shared__ float  swt[8][32];

    for (int i = threadIdx.x; i < HD * COUT; i += blockDim.x) {
        sWl[i] = Wl[i];
        sWr[i] = Wr[i];
    }
    for (int i = threadIdx.x; i < COUT; i += blockDim.x) sb[i] = bl[i];
    __syncthreads();

    int warp = threadIdx.x >> 5;
    int lane = threadIdx.x & 31;
    int node = blockIdx.x * 8 + warp;
    if (node >= n) return;   // whole warp exits together

    int start = g_rowstart[node];
    int end   = g_rowstart[node + 1];

    float a0 = 0.0f, a1 = 0.0f;
    for (int i0 = start; i0 < end; i0 += 32) {
        int m = min(32, end - i0);
        if (lane < m) {
            sid[warp][lane] = g_csrc[i0 + lane];
            swt[warp][lane] = USE_W ? g_cw[i0 + lane] : 1.0f;
        }
        __syncwarp();
#pragma unroll 4
        for (int j = 0; j < m; ++j) {
            int   s = sid[warp][j];
            float w = swt[warp][j];
            float2 v = *(const float2*)(hin + (size_t)s * HD + 2 * lane);
            a0 = fmaf(w, v.x, a0);
            a1 = fmaf(w, v.y, a1);
        }
        __syncwarp();
    }

    float invd = 1.0f / fmaxf((float)(end - start), 1.0f);
    float2 hr = *(const float2*)(hin + (size_t)node * HD + 2 * lane);
    smv[warp][2 * lane]     = make_float2(a0 * invd, hr.x);
    smv[warp][2 * lane + 1] = make_float2(a1 * invd, hr.y);
    __syncwarp();

    if (COUT == 64) {
        int f0 = 2 * lane;
        float o0 = sb[f0], o1 = sb[f0 + 1];
#pragma unroll
        for (int k = 0; k < HD; ++k) {
            float2 mv = smv[warp][k];
            float2 wl = *(const float2*)(sWl + k * COUT + f0);
            float2 wr = *(const float2*)(sWr + k * COUT + f0);
            o0 = fmaf(mv.x, wl.x, o0); o0 = fmaf(mv.y, wr.x, o0);
            o1 = fmaf(mv.x, wl.y, o1); o1 = fmaf(mv.y, wr.y, o1);
        }
        float s = o0 * o0 + o1 * o1;
#pragma unroll
        for (int off = 16; off; off >>= 1) s += __shfl_xor_sync(~0u, s, off);
        float inv = 1.0f / fmaxf(sqrtf(s), 1e-12f);
        o0 *= inv; o1 *= inv;
        if (RELU) { o0 = fmaxf(o0, 0.0f); o1 = fmaxf(o1, 0.0f); }
        *(float2*)(hout + (size_t)node * HD + f0) = make_float2(o0, o1);
    } else {
        float o = (lane < COUT) ? sb[lane] : 0.0f;
#pragma unroll
        for (int k = 0; k < HD; ++k) {
            float2 mv = smv[warp][k];
            if (lane < COUT) {
                o = fmaf(mv.x, sWl[k * COUT + lane], o);
                o = fmaf(mv.y, sWr[k * COUT + lane], o);
            }
        }
        float s = (lane < COUT) ? o * o : 0.0f;
#pragma unroll
        for (int off = 16; off; off >>= 1) s += __shfl_xor_sync(~0u, s, off);
        float inv = 1.0f / fmaxf(sqrtf(s), 1e-12f);
        if (lane < COUT) hout[(size_t)node * COUT + lane] = o * inv;
    }
}

// ---------------- launch ------------------------------------------------------
extern "C" void kernel_launch(void* const* d_in, const int* in_sizes, int n_in,
                              void* d_out, int out_size) {
    const float* x    = (const float*)d_in[0];
    const int*   ei   = (const int*)d_in[1];     // int32 [2, E] (JAX x64 disabled)
    const float* ew   = (const float*)d_in[2];
    const float* embW = (const float*)d_in[3];
    const float* embB = (const float*)d_in[4];
    const float* Wl1 = (const float*)d_in[5];
    const float* bl1 = (const float*)d_in[6];
    const float* Wr1 = (const float*)d_in[7];
    const float* Wl2 = (const float*)d_in[8];
    const float* bl2 = (const float*)d_in[9];
    const float* Wr2 = (const float*)d_in[10];
    const float* Wl3 = (const float*)d_in[11];
    const float* bl3 = (const float*)d_in[12];
    const float* Wr3 = (const float*)d_in[13];
    const float* Wl4 = (const float*)d_in[14];
    const float* bl4 = (const float*)d_in[15];
    const float* Wr4 = (const float*)d_in[16];

    int n = in_sizes[0] / FIN;   // nodes
    int e = in_sizes[2];         // edges (edge_weight count)

    float* hA; float* hB; int* cnt;
    cudaGetSymbolAddress((void**)&hA, g_hA);
    cudaGetSymbolAddress((void**)&hB, g_hB);
    cudaGetSymbolAddress((void**)&cnt, g_cnt);

    cudaMemsetAsync(cnt, 0, (size_t)n * sizeof(int));

    embed_kernel<<<(n * HD + 255) / 256, 256>>>(x, embW, embB, hA, n);
    hist_kernel<<<(e + 255) / 256, 256>>>(ei, e, n);
    scan_kernel<<<1, 1024>>>(n);
    fill_kernel<<<(e + 255) / 256, 256>>>(ei, ew, e, n);

    int grid = (n + 7) / 8;
    sage_kernel<64, true,  true ><<<grid, 256>>>(hA, Wl1, bl1, Wr1, hB, n);
    sage_kernel<64, true,  true ><<<grid, 256>>>(hB, Wl2, bl2, Wr2, hA, n);
    sage_kernel<64, true,  true ><<<grid, 256>>>(hA, Wl3, bl3, Wr3, hB, n);
    sage_kernel<18, false, false><<<grid, 256>>>(hB, Wl4, bl4, Wr4, (float*)d_out, n);
}